// round 12
// baseline (speedup 1.0000x reference)
#include <cuda_runtime.h>
#include <cuda_bf16.h>
#include <cstdint>

// Sliding-window attention via mma.sync fp16 (fp32 accumulate).
// B=2, S=8192, D=64, window +/-64.
// CTA = 128 queries, 16 warps: 8 row-groups x 2 band-half warps.
// Masks only on band-edge tiles (2 of 10 / 2 of 8 per half; single inequality
// each) -- interior tiles are provably fully valid. P packed to fp16 in the
// exp loop. STS.128 fill. Output store split across the warp pair.
constexpr int Sc = 8192;
constexpr int Dc = 64;
constexpr int TQ = 128;
constexpr int NKC = 256;
constexpr int THREADS = 512;
constexpr float SCALE2 = 0.18033688f;  // 2^-3 * log2(e); exp done as ex2
constexpr int PITCH = 144;     // 16-aligned, mod 128 = 16 -> conflict-free

constexpr int SM_KH = 0;                      // fp16 K, 256 rows
constexpr int SM_VH = NKC * PITCH;            // 36864, fp16 V
constexpr int SM_TOTAL = 2 * NKC * PITCH;     // 73728

#define LDSM_X4(r0, r1, r2, r3, addr) \
    asm volatile("ldmatrix.sync.aligned.m8n8.x4.shared.b16 {%0,%1,%2,%3}, [%4];" \
                 : "=r"(r0), "=r"(r1), "=r"(r2), "=r"(r3) : "r"(addr))

#define LDSM_X4_T(r0, r1, r2, r3, addr) \
    asm volatile("ldmatrix.sync.aligned.m8n8.x4.trans.shared.b16 {%0,%1,%2,%3}, [%4];" \
                 : "=r"(r0), "=r"(r1), "=r"(r2), "=r"(r3) : "r"(addr))

#define MMA_F16(c, a, b0, b1) \
    asm volatile("mma.sync.aligned.m16n8k16.row.col.f32.f16.f16.f32 " \
                 "{%0,%1,%2,%3},{%4,%5,%6,%7},{%8,%9},{%0,%1,%2,%3};" \
                 : "+f"((c)[0]), "+f"((c)[1]), "+f"((c)[2]), "+f"((c)[3]) \
                 : "r"((a)[0]), "r"((a)[1]), "r"((a)[2]), "r"((a)[3]), "r"(b0), "r"(b1))

__device__ __forceinline__ uint32_t smem_u32(const void* p) {
    uint32_t a;
    asm("{ .reg .u64 t; cvta.to.shared.u64 t, %1; cvt.u32.u64 %0, t; }" : "=r"(a) : "l"(p));
    return a;
}

__device__ __forceinline__ float ex2(float x) {
    float r;
    asm("ex2.approx.f32 %0, %1;" : "=f"(r) : "f"(x));
    return r;
}

// fp16x2 pack, a in low half.
__device__ __forceinline__ uint32_t pack_h2(float a, float b) {
    uint32_t r;
    asm("cvt.rn.f16x2.f32 %0, %1, %2;" : "=r"(r) : "f"(b), "f"(a));
    return r;
}

// QK over this half's n8-tile pairs; dt OUTER so accumulator chains interleave.
template<int NTPB, int NTPC>
__device__ __forceinline__ void qk_half(uint32_t smb, int m0, int krow, int kcol,
                                        const uint32_t (&qh)[4][4],
                                        float (&sacc)[10][4])
{
    #pragma unroll
    for (int dt = 0; dt < 4; ++dt) {
        #pragma unroll
        for (int i = 0; i < NTPC; ++i) {
            const int rowb = (m0 + (NTPB + i) * 16 + krow) * PITCH;
            const int colb = (dt * 16 + kcol) * 2;
            uint32_t kh0, kh1, kh2, kh3;
            LDSM_X4(kh0, kh1, kh2, kh3, smb + SM_KH + rowb + colb);
            MMA_F16(sacc[2 * i],     qh[dt], kh0, kh1);
            MMA_F16(sacc[2 * i + 1], qh[dt], kh2, kh3);
        }
    }
}

// exp + mask + denominator + fp16 pack for one n8 tile.
// MODE 0: interior tile, provably valid for every lane (no predicates).
// MODE 1: lower band edge (tiles 0,1): only jr >= row can fail.
// MODE 2: upper band edge (tiles 16,17): only jr <= row+128 can fail.
// MODE 3: border CTA: full window + global bounds checks.
template<int MODE>
__device__ __forceinline__ void exp_t(int T, int ts, int m0, int qrow, int jc,
                                      const float (&s)[4], uint32_t (&ph2)[2],
                                      float& dA, float& dB, float& dC, float& dD)
{
    const int jr = T * 8 + jc;
    float p0, p1, p2, p3;
    if (MODE == 0) {
        p0 = ex2(s[0]); p1 = ex2(s[1]); p2 = ex2(s[2]); p3 = ex2(s[3]);
    } else {
        bool v0, v1, v2, v3;
        if (MODE == 1) {
            v0 = jr >= qrow;      v1 = jr + 1 >= qrow;
            v2 = jr >= qrow + 8;  v3 = jr + 1 >= qrow + 8;
        } else if (MODE == 2) {
            v0 = jr <= qrow + 128; v1 = jr + 1 <= qrow + 128;
            v2 = jr <= qrow + 136; v3 = jr + 1 <= qrow + 136;
        } else {
            const int g0 = ts - 64 + m0 + jr;
            const bool b0 = (unsigned)g0 < (unsigned)Sc;
            const bool b1 = (unsigned)(g0 + 1) < (unsigned)Sc;
            v0 = (jr >= qrow) && (jr <= qrow + 128) && b0;
            v1 = (jr + 1 >= qrow) && (jr + 1 <= qrow + 128) && b1;
            v2 = (jr >= qrow + 8) && (jr <= qrow + 136) && b0;
            v3 = (jr + 1 >= qrow + 8) && (jr + 1 <= qrow + 136) && b1;
        }
        p0 = v0 ? ex2(s[0]) : 0.f;
        p1 = v1 ? ex2(s[1]) : 0.f;
        p2 = v2 ? ex2(s[2]) : 0.f;
        p3 = v3 ? ex2(s[3]) : 0.f;
    }
    dA += p0; dB += p1; dC += p2; dD += p3;
    ph2[0] = pack_h2(p0, p1);   // rows qrow   : A-frag low pair
    ph2[1] = pack_h2(p2, p3);   // rows qrow+8
}

// PV single-term fp16: P fragments already packed (ph), V from fp16 buffer.
template<int KTB, int KTC>
__device__ __forceinline__ void pv_half(uint32_t smb, int m0, int vrow, int vcol,
                                        const uint32_t (&ph)[10][2],
                                        float (&oacc)[8][4])
{
    #pragma unroll
    for (int k = 0; k < KTC; ++k) {
        const uint32_t ah[4] = { ph[2 * k][0], ph[2 * k][1],
                                 ph[2 * k + 1][0], ph[2 * k + 1][1] };
        const int rowb = (m0 + (KTB + k) * 16 + vrow) * PITCH;
        #pragma unroll
        for (int dp = 0; dp < 4; ++dp) {
            const int colb = (dp * 16 + vcol) * 2;
            uint32_t vh0, vh1, vh2, vh3;
            LDSM_X4_T(vh0, vh1, vh2, vh3, smb + SM_VH + rowb + colb);
            MMA_F16(oacc[2 * dp],     ah, vh0, vh1);
            MMA_F16(oacc[2 * dp + 1], ah, vh2, vh3);
        }
    }
}

template<bool INTERIOR>
__device__ __forceinline__ void body(const float* __restrict__ qg,
                                     const float* __restrict__ kg,
                                     const float* __restrict__ vg,
                                     float* __restrict__ outg,
                                     char* smem, uint32_t smb, int ts, size_t gbase)
{
    const int t = threadIdx.x;
    const int l = t & 31;
    const int grp = (t >> 6);      // row group (16 rows each), 0..7
    const int half = (t >> 5) & 1; // band half: 0 -> tiles 0-9, 1 -> tiles 10-17
    const int m0 = grp * 16;
    const int qrow = l >> 2;
    const int jc = (l & 3) * 2;

    // ---- Q fragments from gmem with 2^-3*log2e folded in, fp16 pack ----
    uint32_t qh[4][4];
    {
        const float* qb = qg + gbase + (size_t)(ts + m0 + qrow) * Dc + jc;
        #pragma unroll
        for (int dt = 0; dt < 4; ++dt) {
            const float2 f0 = *(const float2*)(qb + dt * 16);
            const float2 f1 = *(const float2*)(qb + 8 * Dc + dt * 16);
            const float2 f2 = *(const float2*)(qb + dt * 16 + 8);
            const float2 f3 = *(const float2*)(qb + 8 * Dc + dt * 16 + 8);
            qh[dt][0] = pack_h2(f0.x * SCALE2, f0.y * SCALE2);
            qh[dt][1] = pack_h2(f1.x * SCALE2, f1.y * SCALE2);
            qh[dt][2] = pack_h2(f2.x * SCALE2, f2.y * SCALE2);
            qh[dt][3] = pack_h2(f3.x * SCALE2, f3.y * SCALE2);
        }
    }

    // ---- Cooperative fill: 2 adjacent 16B chunks per thread -> STS.128 ----
    #pragma unroll
    for (int i = 0; i < 4; ++i) {
        const int p = t + i * THREADS;    // 0..2047 chunk-pairs
        const int row = p >> 3;
        const int c8 = (p & 7) << 1;      // even c4 index
        const int g = ts - 64 + row;
        float4 k0, k1, v0, v1;
        if (INTERIOR || (unsigned)g < (unsigned)Sc) {
            const size_t goff = gbase + (size_t)g * Dc + c8 * 4;
            k0 = *(const float4*)(kg + goff);
            k1 = *(const float4*)(kg + goff + 4);
            v0 = *(const float4*)(vg + goff);
            v1 = *(const float4*)(vg + goff + 4);
        } else {
            k0 = k1 = v0 = v1 = make_float4(0.f, 0.f, 0.f, 0.f);
        }
        const int off = row * PITCH + c8 * 8;   // 16B aligned (144 = 16*9)
        *(uint4*)(smem + SM_KH + off) = make_uint4(
            pack_h2(k0.x, k0.y), pack_h2(k0.z, k0.w),
            pack_h2(k1.x, k1.y), pack_h2(k1.z, k1.w));
        *(uint4*)(smem + SM_VH + off) = make_uint4(
            pack_h2(v0.x, v0.y), pack_h2(v0.z, v0.w),
            pack_h2(v1.x, v1.y), pack_h2(v1.z, v1.w));
    }
    __syncthreads();

    // ---- QK on this warp's band half ----
    float sacc[10][4];
    #pragma unroll
    for (int i = 0; i < 10; ++i)
        #pragma unroll
        for (int c = 0; c < 4; ++c) sacc[i][c] = 0.f;

    const int krow = (l & 7) + ((l >> 4) << 3);
    const int kcol = ((l >> 3) & 1) << 3;
    if (half == 0) qk_half<0, 5>(smb, m0, krow, kcol, qh, sacc);
    else           qk_half<5, 4>(smb, m0, krow, kcol, qh, sacc);

    // ---- exp + mask (edge tiles only) + pack to fp16 fragments ----
    uint32_t ph[10][2];
    float dA = 0.f, dB = 0.f, dC = 0.f, dD = 0.f;
    if (INTERIOR) {
        if (half == 0) {
            exp_t<1>(0, ts, m0, qrow, jc, sacc[0], ph[0], dA, dB, dC, dD);
            exp_t<1>(1, ts, m0, qrow, jc, sacc[1], ph[1], dA, dB, dC, dD);
            #pragma unroll
            for (int i = 2; i < 10; ++i)
                exp_t<0>(i, ts, m0, qrow, jc, sacc[i], ph[i], dA, dB, dC, dD);
        } else {
            #pragma unroll
            for (int i = 0; i < 6; ++i)
                exp_t<0>(10 + i, ts, m0, qrow, jc, sacc[i], ph[i], dA, dB, dC, dD);
            exp_t<2>(16, ts, m0, qrow, jc, sacc[6], ph[6], dA, dB, dC, dD);
            exp_t<2>(17, ts, m0, qrow, jc, sacc[7], ph[7], dA, dB, dC, dD);
        }
    } else {
        if (half == 0) {
            #pragma unroll
            for (int i = 0; i < 10; ++i)
                exp_t<3>(i, ts, m0, qrow, jc, sacc[i], ph[i], dA, dB, dC, dD);
        } else {
            #pragma unroll
            for (int i = 0; i < 8; ++i)
                exp_t<3>(10 + i, ts, m0, qrow, jc, sacc[i], ph[i], dA, dB, dC, dD);
        }
    }
    float den0 = dA + dB;
    float den1 = dC + dD;
    den0 += __shfl_xor_sync(0xffffffffu, den0, 1);
    den0 += __shfl_xor_sync(0xffffffffu, den0, 2);
    den1 += __shfl_xor_sync(0xffffffffu, den1, 1);
    den1 += __shfl_xor_sync(0xffffffffu, den1, 2);

    // ---- PV on this warp's band half ----
    float oacc[8][4];
    #pragma unroll
    for (int i = 0; i < 8; ++i)
        #pragma unroll
        for (int c = 0; c < 4; ++c) oacc[i][c] = 0.f;

    const int vrow = l & 15;
    const int vcol = (l >> 4) << 3;
    if (half == 0) pv_half<0, 5>(smb, m0, vrow, vcol, ph, oacc);
    else           pv_half<5, 4>(smb, m0, vrow, vcol, ph, oacc);

    // ---- Split exchange+store: half0 stores cols 0-31, half1 cols 32-63 ----
    __syncthreads();   // all QK/PV smem reads done; K region becomes scratch
    const uint32_t grpbase = (uint32_t)grp * 4608u;          // 8*4608 = 36864
    const uint32_t mybase = grpbase + (uint32_t)half * 2304u;
    const uint32_t otbase = grpbase + (uint32_t)(half ^ 1) * 2304u;
    const int sendbase = half ? 0 : 4;   // tiles the PARTNER will store
    #pragma unroll
    for (int d = 0; d < 4; ++d)
        *(float4*)(smem + mybase + (uint32_t)(d * 32 + l) * 16u) =
            make_float4(oacc[sendbase + d][0], oacc[sendbase + d][1],
                        oacc[sendbase + d][2], oacc[sendbase + d][3]);
    if ((l & 3) == 0) {
        *(float*)(smem + mybase + 2048 + qrow * 8)     = den0;
        *(float*)(smem + mybase + 2048 + qrow * 8 + 4) = den1;
    }
    __syncthreads();

    const int keepbase = half ? 4 : 0;
    den0 += *(const float*)(smem + otbase + 2048 + qrow * 8);
    den1 += *(const float*)(smem + otbase + 2048 + qrow * 8 + 4);
    const float inv0 = 1.f / den0;
    const float inv1 = 1.f / den1;
    float* row0 = outg + gbase + (size_t)(ts + m0 + qrow) * Dc;
    float* row1 = row0 + 8 * Dc;
    #pragma unroll
    for (int d = 0; d < 4; ++d) {
        const float4 pp = *(const float4*)(smem + otbase + (uint32_t)(d * 32 + l) * 16u);
        const int dt = keepbase + d;
        const int col = dt * 8 + jc;
        *(float2*)(row0 + col) = make_float2((oacc[dt][0] + pp.x) * inv0,
                                             (oacc[dt][1] + pp.y) * inv0);
        *(float2*)(row1 + col) = make_float2((oacc[dt][2] + pp.z) * inv1,
                                             (oacc[dt][3] + pp.w) * inv1);
    }
}

__global__ __launch_bounds__(THREADS, 1)
void swa_mma_kernel(const float* __restrict__ qg, const float* __restrict__ kg,
                    const float* __restrict__ vg, float* __restrict__ outg)
{
    extern __shared__ char smem[];
    const uint32_t smb = smem_u32(smem);
    const int ts = blockIdx.x * TQ;
    const size_t gbase = (size_t)blockIdx.y * Sc * Dc;

    if (ts >= 64 && ts + TQ + 64 <= Sc)
        body<true>(qg, kg, vg, outg, smem, smb, ts, gbase);
    else
        body<false>(qg, kg, vg, outg, smem, smb, ts, gbase);
}

extern "C" void kernel_launch(void* const* d_in, const int* in_sizes, int n_in,
                              void* d_out, int out_size)
{
    const float* q = (const float*)d_in[0];
    const float* k = (const float*)d_in[1];
    const float* v = (const float*)d_in[2];
    float* out = (float*)d_out;

    cudaFuncSetAttribute(swa_mma_kernel, cudaFuncAttributeMaxDynamicSharedMemorySize, SM_TOTAL);
    dim3 grid(Sc / TQ, 2);   // 64 x 2 = 128 CTAs, 16 warps each
    swa_mma_kernel<<<grid, THREADS, SM_TOTAL>>>(q, k, v, out);
}